// round 1
// baseline (speedup 1.0000x reference)
#include <cuda_runtime.h>
#include <cuda_bf16.h>

#define B_ 32
#define S_ 2048
#define H_ 1024
#define L_ 32

// denominator scratch (no device allocs allowed)
__device__ float g_den[B_];

// ---------------------------------------------------------------------------
// Kernel 1: logits = hidden @ W + b   (M=65536, K=1024, N=32, fp32)
// Block: 256 threads computes 128 rows x 32 cols. K tiled by 32.
// hs is [row][kk] (row-major, stride 32): STS.128 conflict-free, inner-loop
// LDS.128 is a 2-address broadcast (conflict-free).
// ---------------------------------------------------------------------------
__global__ __launch_bounds__(256) void gemm_kernel(
    const float* __restrict__ hidden,
    const float* __restrict__ W,
    const float* __restrict__ bias,
    float* __restrict__ out)
{
    __shared__ __align__(16) float hs[128 * 32];
    __shared__ __align__(16) float ws[32 * 32];

    const int tid  = threadIdx.x;
    const int R0   = blockIdx.x * 128;
    const int cp   = (tid & 15) * 2;   // column pair base (0..30, even)
    const int rg   = (tid >> 4) * 8;   // row base within tile (0..120)
    const int lrow = tid >> 3;         // load row / W row (0..31)
    const int lk4  = (tid & 7) * 4;    // load k offset (0..28)

    float acc[8][2];
#pragma unroll
    for (int r = 0; r < 8; r++) { acc[r][0] = 0.f; acc[r][1] = 0.f; }

    for (int kt = 0; kt < H_; kt += 32) {
        // hidden tile: 128 rows x 32 k, coalesced float4 loads
#pragma unroll
        for (int rr = 0; rr < 128; rr += 32) {
            float4 v = *(const float4*)(hidden + (size_t)(R0 + lrow + rr) * H_ + kt + lk4);
            *(float4*)(hs + (lrow + rr) * 32 + lk4) = v;
        }
        // W tile: 32 k x 32 cols
        {
            float4 wv = *(const float4*)(W + (size_t)(kt + lrow) * L_ + lk4);
            *(float4*)(ws + lrow * 32 + lk4) = wv;
        }
        __syncthreads();

#pragma unroll
        for (int kk4 = 0; kk4 < 32; kk4 += 4) {
            float4 h[8];
#pragma unroll
            for (int r = 0; r < 8; r++)
                h[r] = *(const float4*)(hs + (rg + r) * 32 + kk4);
#pragma unroll
            for (int i = 0; i < 4; i++) {
                float2 wv = *(const float2*)(ws + (kk4 + i) * 32 + cp);
#pragma unroll
                for (int r = 0; r < 8; r++) {
                    float hv = (i == 0) ? h[r].x : (i == 1) ? h[r].y : (i == 2) ? h[r].z : h[r].w;
                    acc[r][0] = fmaf(hv, wv.x, acc[r][0]);
                    acc[r][1] = fmaf(hv, wv.y, acc[r][1]);
                }
            }
        }
        __syncthreads();
    }

    const float b0 = bias[cp];
    const float b1 = bias[cp + 1];
#pragma unroll
    for (int r = 0; r < 8; r++) {
        out[(size_t)(R0 + rg + r) * L_ + cp]     = acc[r][0] + b0;
        out[(size_t)(R0 + rg + r) * L_ + cp + 1] = acc[r][1] + b1;
    }
}

// ---------------------------------------------------------------------------
// Kernel 2: CRF forward (denominator). One warp per batch, lane = state j.
// Linear-space recurrence A <- (sum_i A_i * exp(T_ij)) * exp(em_tj),
// renormalized every 8 steps; logsumexp recovered exactly at the end.
// em/mask prefetched 8 steps ahead to keep L2 latency off the serial chain.
// ---------------------------------------------------------------------------
__global__ void scan_kernel(
    const float* __restrict__ logits,
    const int*   __restrict__ mask,
    const float* __restrict__ trans,
    const float* __restrict__ start,
    const float* __restrict__ endt)
{
    const int b = blockIdx.x;
    const int j = threadIdx.x;
    const float* lg = logits + (size_t)b * S_ * L_;
    const int*   mk = mask + (size_t)b * S_;

    float et[32];
#pragma unroll
    for (int i = 0; i < 32; i++) et[i] = __expf(trans[i * L_ + j]);

    // init alpha_0 = start + em_0, normalized
    float a0 = start[j] + lg[j];
    float mx = a0;
#pragma unroll
    for (int off = 16; off > 0; off >>= 1)
        mx = fmaxf(mx, __shfl_xor_sync(0xffffffffu, mx, off));
    float A    = __expf(a0 - mx);
    float logz = mx;

    // software-pipelined em/mask prefetch (depth 8)
    float emb[8];
    int   mb[8];
#pragma unroll
    for (int u = 0; u < 8; u++) {
        emb[u] = lg[(size_t)(1 + u) * L_ + j];
        mb[u]  = mk[1 + u];
    }

    int t = 1;
    for (int blk = 0; blk < 255; blk++) {   // covers t = 1..2040
#pragma unroll
        for (int u = 0; u < 8; u++) {
            float s0 = 0.f, s1 = 0.f, s2 = 0.f, s3 = 0.f;
#pragma unroll
            for (int i = 0; i < 32; i += 4) {
                s0 = fmaf(__shfl_sync(0xffffffffu, A, i),     et[i],     s0);
                s1 = fmaf(__shfl_sync(0xffffffffu, A, i + 1), et[i + 1], s1);
                s2 = fmaf(__shfl_sync(0xffffffffu, A, i + 2), et[i + 2], s2);
                s3 = fmaf(__shfl_sync(0xffffffffu, A, i + 3), et[i + 3], s3);
            }
            float nA = ((s0 + s1) + (s2 + s3)) * __expf(emb[u]);
            A = (mb[u] > 0) ? nA : A;
            int tn = t + u + 8;
            if (tn < S_) {
                emb[u] = lg[(size_t)tn * L_ + j];
                mb[u]  = mk[tn];
            }
        }
        // renormalize (every 8 steps): keep max(A) = 1
        float m2 = A;
#pragma unroll
        for (int off = 16; off > 0; off >>= 1)
            m2 = fmaxf(m2, __shfl_xor_sync(0xffffffffu, m2, off));
        A *= (1.0f / m2);
        logz += __logf(m2);
        t += 8;
    }

    // tail: t = 2041..2047 (7 steps), emb/mb already loaded
#pragma unroll
    for (int u = 0; u < 7; u++) {
        float s0 = 0.f, s1 = 0.f, s2 = 0.f, s3 = 0.f;
#pragma unroll
        for (int i = 0; i < 32; i += 4) {
            s0 = fmaf(__shfl_sync(0xffffffffu, A, i),     et[i],     s0);
            s1 = fmaf(__shfl_sync(0xffffffffu, A, i + 1), et[i + 1], s1);
            s2 = fmaf(__shfl_sync(0xffffffffu, A, i + 2), et[i + 2], s2);
            s3 = fmaf(__shfl_sync(0xffffffffu, A, i + 3), et[i + 3], s3);
        }
        float nA = ((s0 + s1) + (s2 + s3)) * __expf(emb[u]);
        A = (mb[u] > 0) ? nA : A;
    }

    // denominator = logz + log(sum_j A_j * exp(end_j))
    float v = A * __expf(endt[j]);
#pragma unroll
    for (int off = 16; off > 0; off >>= 1)
        v += __shfl_xor_sync(0xffffffffu, v, off);
    if (j == 0) g_den[b] = logz + __logf(v);
}

// ---------------------------------------------------------------------------
// Kernel 3: numerator per batch (one warp each) + final loss reduce.
// ---------------------------------------------------------------------------
__global__ void loss_kernel(
    const float* __restrict__ logits,
    const int*   __restrict__ labels,
    const int*   __restrict__ mask,
    const float* __restrict__ trans,
    const float* __restrict__ start,
    const float* __restrict__ endt,
    float* __restrict__ loss_out)
{
    __shared__ float sh[B_];
    const int tid  = threadIdx.x;
    const int b    = tid >> 5;
    const int lane = tid & 31;
    const int*   lb = labels + (size_t)b * S_;
    const int*   mk = mask + (size_t)b * S_;
    const float* lg = logits + (size_t)b * S_ * L_;

    float part = 0.f;
    int   msum = 0;
    for (int t = lane; t < S_; t += 32) msum += (mk[t] > 0);
    for (int t = 1 + lane; t < S_; t += 32) {
        if (mk[t] > 0) {
            int cur = lb[t], prev = lb[t - 1];
            part += lg[(size_t)t * L_ + cur] + trans[prev * L_ + cur];
        }
    }
#pragma unroll
    for (int off = 16; off > 0; off >>= 1) {
        part += __shfl_xor_sync(0xffffffffu, part, off);
        msum += __shfl_xor_sync(0xffffffffu, msum, off);
    }
    if (lane == 0) {
        int first = lb[0];
        int last  = lb[msum - 1];
        float num = start[first] + lg[first] + part + endt[last];
        sh[b] = num - g_den[b];
    }
    __syncthreads();
    if (tid < 32) {
        float v = sh[tid];
#pragma unroll
        for (int off = 16; off > 0; off >>= 1)
            v += __shfl_xor_sync(0xffffffffu, v, off);
        if (tid == 0) loss_out[0] = -(v * (1.0f / B_));
    }
}

// ---------------------------------------------------------------------------
extern "C" void kernel_launch(void* const* d_in, const int* in_sizes, int n_in,
                              void* d_out, int out_size)
{
    const float* hidden = (const float*)d_in[0];
    const float* W      = (const float*)d_in[1];
    const float* bias   = (const float*)d_in[2];
    const float* trans  = (const float*)d_in[3];
    const float* start  = (const float*)d_in[4];
    const float* endt   = (const float*)d_in[5];
    const int*   labels = (const int*)d_in[6];
    const int*   mask   = (const int*)d_in[7];

    float* out    = (float*)d_out;
    float* logits = out + 1;   // d_out = [loss, logits...]

    gemm_kernel<<<(B_ * S_) / 128, 256>>>(hidden, W, bias, logits);
    scan_kernel<<<B_, 32>>>(logits, mask, trans, start, endt);
    loss_kernel<<<1, B_ * 32>>>(logits, labels, mask, trans, start, endt, out);
}

// round 2
// speedup vs baseline: 2.6124x; 2.6124x over previous
#include <cuda_runtime.h>
#include <cuda_bf16.h>

#define B_ 32
#define S_ 2048
#define H_ 1024
#define L_ 32

// scratch (no device allocs allowed)
__device__ float g_fvec[B_][L_];
__device__ float g_bvec[B_][L_];
__device__ int   g_fez[B_];
__device__ int   g_bez[B_];

// ---- packed f32x2 helpers (Blackwell) --------------------------------------
__device__ __forceinline__ unsigned long long ffma2(unsigned long long a,
                                                    unsigned long long b,
                                                    unsigned long long c) {
    unsigned long long d;
    asm("fma.rn.f32x2 %0, %1, %2, %3;" : "=l"(d) : "l"(a), "l"(b), "l"(c));
    return d;
}
__device__ __forceinline__ unsigned long long fadd2(unsigned long long a,
                                                    unsigned long long b) {
    unsigned long long d;
    asm("add.rn.f32x2 %0, %1, %2;" : "=l"(d) : "l"(a), "l"(b));
    return d;
}
__device__ __forceinline__ unsigned long long fpack2(float lo, float hi) {
    unsigned long long d;
    asm("mov.b64 %0, {%1, %2};" : "=l"(d) : "f"(lo), "f"(hi));
    return d;
}
__device__ __forceinline__ float funpack_add(unsigned long long a) {
    float lo, hi;
    asm("mov.b64 {%0, %1}, %2;" : "=f"(lo), "=f"(hi) : "l"(a));
    return lo + hi;
}

// ---------------------------------------------------------------------------
// Kernel 1: logits = hidden @ W + b   (M=65536, K=1024, N=32, fp32)
// (unchanged from round 1 — 155us, tackled next round)
// ---------------------------------------------------------------------------
__global__ __launch_bounds__(256) void gemm_kernel(
    const float* __restrict__ hidden,
    const float* __restrict__ W,
    const float* __restrict__ bias,
    float* __restrict__ out)
{
    __shared__ __align__(16) float hs[128 * 32];
    __shared__ __align__(16) float ws[32 * 32];

    const int tid  = threadIdx.x;
    const int R0   = blockIdx.x * 128;
    const int cp   = (tid & 15) * 2;
    const int rg   = (tid >> 4) * 8;
    const int lrow = tid >> 3;
    const int lk4  = (tid & 7) * 4;

    float acc[8][2];
#pragma unroll
    for (int r = 0; r < 8; r++) { acc[r][0] = 0.f; acc[r][1] = 0.f; }

    for (int kt = 0; kt < H_; kt += 32) {
#pragma unroll
        for (int rr = 0; rr < 128; rr += 32) {
            float4 v = *(const float4*)(hidden + (size_t)(R0 + lrow + rr) * H_ + kt + lk4);
            *(float4*)(hs + (lrow + rr) * 32 + lk4) = v;
        }
        {
            float4 wv = *(const float4*)(W + (size_t)(kt + lrow) * L_ + lk4);
            *(float4*)(ws + lrow * 32 + lk4) = wv;
        }
        __syncthreads();

#pragma unroll
        for (int kk4 = 0; kk4 < 32; kk4 += 4) {
            float4 h[8];
#pragma unroll
            for (int r = 0; r < 8; r++)
                h[r] = *(const float4*)(hs + (rg + r) * 32 + kk4);
#pragma unroll
            for (int i = 0; i < 4; i++) {
                float2 wv = *(const float2*)(ws + (kk4 + i) * 32 + cp);
#pragma unroll
                for (int r = 0; r < 8; r++) {
                    float hv = (i == 0) ? h[r].x : (i == 1) ? h[r].y : (i == 2) ? h[r].z : h[r].w;
                    acc[r][0] = fmaf(hv, wv.x, acc[r][0]);
                    acc[r][1] = fmaf(hv, wv.y, acc[r][1]);
                }
            }
        }
        __syncthreads();
    }

    const float b0 = bias[cp];
    const float b1 = bias[cp + 1];
#pragma unroll
    for (int r = 0; r < 8; r++) {
        out[(size_t)(R0 + rg + r) * L_ + cp]     = acc[r][0] + b0;
        out[(size_t)(R0 + rg + r) * L_ + cp + 1] = acc[r][1] + b1;
    }
}

// ---------------------------------------------------------------------------
// Kernel 2: CRF forward/backward half-scans. 64 warps: blockIdx<32 = forward
// chain of batch b (t=1..1023 real + 1 dead step), blockIdx>=32 = backward
// chain (t=2047..1024). Linear space, smem all-to-all exchange, f32x2 dots,
// power-of-two renorm every 8 steps with integer exponent accounting.
// Z_b = sum_i a_fwd[i] * v_bwd[i] * 2^(ezF+ezB), combined in loss_kernel.
// ---------------------------------------------------------------------------
__global__ void scan_kernel(
    const float* __restrict__ logits,
    const int*   __restrict__ mask,
    const float* __restrict__ trans,
    const float* __restrict__ start,
    const float* __restrict__ endt)
{
    __shared__ __align__(16) float buf[2][L_];
    const int b   = blockIdx.x & (B_ - 1);
    const int dir = blockIdx.x >> 5;   // 0 = forward, 1 = backward
    const int j   = threadIdx.x;
    const float* lg = logits + (size_t)b * S_ * L_;
    const int*   mk = mask + (size_t)b * S_;

    // exp(transitions), packed as f32x2 pairs.
    // forward (lane = dest state j): pairs over source i -> column j
    // backward (lane = state i):     pairs over dest j   -> row i
    unsigned long long etp[16];
    if (dir == 0) {
#pragma unroll
        for (int u = 0; u < 16; u++)
            etp[u] = fpack2(__expf(trans[(2 * u) * L_ + j]),
                            __expf(trans[(2 * u + 1) * L_ + j]));
    } else {
#pragma unroll
        for (int u = 0; u < 16; u++)
            etp[u] = fpack2(__expf(trans[j * L_ + 2 * u]),
                            __expf(trans[j * L_ + 2 * u + 1]));
    }

    float A = (dir == 0) ? __expf(start[j] + lg[j]) : __expf(endt[j]);
    int   ez = 0;
    int   p  = 0;

    // prefetch ring (depth 8): em already exponentiated -> MUFU off the chain
    float emb[8];
    int   mb[8];
#pragma unroll
    for (int u = 0; u < 8; u++) {
        int t = (dir == 0) ? (1 + u) : (S_ - 1 - u);
        emb[u] = __expf(lg[(size_t)t * L_ + j]);
        mb[u]  = mk[t];
    }

    for (int blk = 0; blk < 128; blk++) {
#pragma unroll
        for (int u = 0; u < 8; u++) {
            const int s = blk * 8 + u;
            // exchange value: fwd = A, bwd = A * exp(em_t) (pre-scale)
            float x = (dir == 0) ? A : A * emb[u];
            buf[p][j] = x;
            __syncwarp();
            const ulonglong2* bp = reinterpret_cast<const ulonglong2*>(buf[p]);
            unsigned long long acc0 = 0ull, acc1 = 0ull, acc2 = 0ull, acc3 = 0ull;
#pragma unroll
            for (int q = 0; q < 4; q++) {
                ulonglong2 v0 = bp[q * 2];
                ulonglong2 v1 = bp[q * 2 + 1];
                acc0 = ffma2(v0.x, etp[q * 4 + 0], acc0);
                acc1 = ffma2(v0.y, etp[q * 4 + 1], acc1);
                acc2 = ffma2(v1.x, etp[q * 4 + 2], acc2);
                acc3 = ffma2(v1.y, etp[q * 4 + 3], acc3);
            }
            float dot  = funpack_add(fadd2(fadd2(acc0, acc1), fadd2(acc2, acc3)));
            float Anew = (dir == 0) ? dot * emb[u] : dot;
            // forward has 1023 real steps; step s==1023 is dead padding
            bool live  = (dir == 1) || (s < 1023);
            A = (mb[u] && live) ? Anew : A;

            if (u == 7) {
                // power-of-two renorm: exponent of buf[p][0] is warp-uniform
                float a0 = fmaxf(buf[p][0], 1e-30f);
                int   sb = (__float_as_int(a0) >> 23) & 0xff;
                A  *= __int_as_float((254 - sb) << 23);  // 2^(127-sb), exact
                ez += sb - 127;
            }
            p ^= 1;
            // prefetch 8 ahead (always in-bounds: fwd t<=1032, bwd t>=1016)
            int tn = (dir == 0) ? (s + 9) : (S_ - 9 - s);
            emb[u] = __expf(lg[(size_t)tn * L_ + j]);
            mb[u]  = mk[tn];
        }
    }

    // final renorm + store
    buf[p][j] = A;
    __syncwarp();
    float a0 = fmaxf(buf[p][0], 1e-30f);
    int   sb = (__float_as_int(a0) >> 23) & 0xff;
    A  *= __int_as_float((254 - sb) << 23);
    ez += sb - 127;
    if (dir == 0) { g_fvec[b][j] = A; if (j == 0) g_fez[b] = ez; }
    else          { g_bvec[b][j] = A; if (j == 0) g_bez[b] = ez; }
}

// ---------------------------------------------------------------------------
// Kernel 3: numerator per batch + denominator combine + final loss reduce.
// ---------------------------------------------------------------------------
__global__ void loss_kernel(
    const float* __restrict__ logits,
    const int*   __restrict__ labels,
    const int*   __restrict__ mask,
    const float* __restrict__ trans,
    const float* __restrict__ start,
    const float* __restrict__ endt,
    float* __restrict__ loss_out)
{
    __shared__ float sh[B_];
    const int tid  = threadIdx.x;
    const int b    = tid >> 5;
    const int lane = tid & 31;
    const int*   lb = labels + (size_t)b * S_;
    const int*   mk = mask + (size_t)b * S_;
    const float* lg = logits + (size_t)b * S_ * L_;

    float part = 0.f;
    int   msum = 0;
    for (int t = lane; t < S_; t += 32) msum += (mk[t] > 0);
    for (int t = 1 + lane; t < S_; t += 32) {
        if (mk[t] > 0) {
            int cur = lb[t], prev = lb[t - 1];
            part += lg[(size_t)t * L_ + cur] + trans[prev * L_ + cur];
        }
    }
    // denominator: dot of forward/backward half-scan states
    float dv = g_fvec[b][lane] * g_bvec[b][lane];
#pragma unroll
    for (int off = 16; off > 0; off >>= 1) {
        part += __shfl_xor_sync(0xffffffffu, part, off);
        msum += __shfl_xor_sync(0xffffffffu, msum, off);
        dv   += __shfl_xor_sync(0xffffffffu, dv, off);
    }
    if (lane == 0) {
        int first = lb[0];
        int last  = lb[msum - 1];
        float num = start[first] + lg[first] + part + endt[last];
        float den = __logf(dv) + (float)(g_fez[b] + g_bez[b]) * 0.69314718056f;
        sh[b] = num - den;
    }
    __syncthreads();
    if (tid < 32) {
        float v = sh[tid];
#pragma unroll
        for (int off = 16; off > 0; off >>= 1)
            v += __shfl_xor_sync(0xffffffffu, v, off);
        if (tid == 0) loss_out[0] = -(v * (1.0f / B_));
    }
}

// ---------------------------------------------------------------------------
extern "C" void kernel_launch(void* const* d_in, const int* in_sizes, int n_in,
                              void* d_out, int out_size)
{
    const float* hidden = (const float*)d_in[0];
    const float* W      = (const float*)d_in[1];
    const float* bias   = (const float*)d_in[2];
    const float* trans  = (const float*)d_in[3];
    const float* start  = (const float*)d_in[4];
    const float* endt   = (const float*)d_in[5];
    const int*   labels = (const int*)d_in[6];
    const int*   mask   = (const int*)d_in[7];

    float* out    = (float*)d_out;
    float* logits = out + 1;   // d_out = [loss, logits...]

    gemm_kernel<<<(B_ * S_) / 128, 256>>>(hidden, W, bias, logits);
    scan_kernel<<<2 * B_, 32>>>(logits, mask, trans, start, endt);
    loss_kernel<<<1, B_ * 32>>>(logits, labels, mask, trans, start, endt, out);
}